// round 2
// baseline (speedup 1.0000x reference)
#include <cuda_runtime.h>
#include <math.h>

#define BB      32768
#define NB      16          // batches per CTA
#define NT      512         // threads per CTA (16 warps, warp == batch)
#define SCALE_ATT 0.125f
#define LN_EPS  1e-5f
#define STR     68          // padded activation row stride (68 % 32 == 4 -> conflict-free)

// Output packing offsets (flat concat of return tuple, C-order)
#define OFF_COLOR 0
#define OFF_SIGMA (3 * BB)
#define OFF_OUT   (OFF_SIGMA + BB)
#define OFF_ATTN  (OFF_OUT + (size_t)BB * 512)

// Shared memory layout (floats)
#define SX_OFF   0              // [128][68] activations
#define ST0_OFF  8704           // [128][68] Q / ctx / ffn-h1 / Kc
#define ST1_OFF  17408          // [128][68] K / Y / Vc
#define ST2_OFF  26112          // [128][68] V / Qc rows
#define SW_OFF   34816          // 16384 : four 4096-float weight slots
#define SP_OFF   51200          // [16][64] probs
#define SQI_OFF  52224          // [16][64] query in
#define SCA_OFF  53248          // [16][64] cross ctx row
#define SMEM_FLOATS 54272       // 217088 bytes

typedef unsigned long long ull;

__device__ __forceinline__ ull pk2(float lo, float hi) {
    ull r;
    asm("mov.b64 %0, {%1, %2};" : "=l"(r) : "r"(__float_as_uint(lo)), "r"(__float_as_uint(hi)));
    return r;
}
__device__ __forceinline__ void fma2(ull &acc, ull a, ull b) {
    asm("fma.rn.f32x2 %0, %1, %2, %0;" : "+l"(acc) : "l"(a), "l"(b));
}
__device__ __forceinline__ float2 upk(ull v) {
    unsigned int lo, hi;
    asm("mov.b64 {%0, %1}, %2;" : "=r"(lo), "=r"(hi) : "l"(v));
    return make_float2(__uint_as_float(lo), __uint_as_float(hi));
}

// ---- cooperative copiers ----
__device__ __forceinline__ void cp_f4(float* __restrict__ dst, const float* __restrict__ src,
                                      int n4, int tid) {
    for (int i = tid; i < n4; i += NT)
        reinterpret_cast<float4*>(dst)[i] = reinterpret_cast<const float4*>(src)[i];
}
// copy a [64][64] head slice out of a [64][256] row-major matrix (src at col h*64)
__device__ __forceinline__ void cp_slice(float* __restrict__ dst, const float* __restrict__ src,
                                         int tid) {
    for (int i = tid; i < 64 * 16; i += NT) {
        int r = i >> 4, c = i & 15;
        reinterpret_cast<float4*>(dst)[i] =
            reinterpret_cast<const float4*>(src + r * 256)[c];
    }
}

// ---- GEMM core: Y[128][64] (+)= X[128][K] @ W[K][64] ----
// thread tile: 2 rows x 8 cols, k-vectorized float4 loads, packed FFMA2
template<int K, int LDX>
__device__ __forceinline__ void gemm_acc8(const float* __restrict__ X,
                                          const float* __restrict__ W,
                                          ull a0[4], ull a1[4], int c0, int rb) {
#pragma unroll 4
    for (int k = 0; k < K; k += 4) {
        float4 x0 = *reinterpret_cast<const float4*>(X + rb * LDX + k);
        float4 x1 = *reinterpret_cast<const float4*>(X + (rb + 1) * LDX + k);
#pragma unroll
        for (int kk = 0; kk < 4; ++kk) {
            float4 wa = *reinterpret_cast<const float4*>(W + (k + kk) * 64 + c0);
            float4 wb = *reinterpret_cast<const float4*>(W + (k + kk) * 64 + c0 + 4);
            ull w01 = pk2(wa.x, wa.y), w23 = pk2(wa.z, wa.w);
            ull w45 = pk2(wb.x, wb.y), w67 = pk2(wb.z, wb.w);
            float xs0 = reinterpret_cast<const float*>(&x0)[kk];
            float xs1 = reinterpret_cast<const float*>(&x1)[kk];
            ull xx0 = pk2(xs0, xs0);
            ull xx1 = pk2(xs1, xs1);
            fma2(a0[0], w01, xx0); fma2(a0[1], w23, xx0);
            fma2(a0[2], w45, xx0); fma2(a0[3], w67, xx0);
            fma2(a1[0], w01, xx1); fma2(a1[1], w23, xx1);
            fma2(a1[2], w45, xx1); fma2(a1[3], w67, xx1);
        }
    }
}

template<bool RELU>
__device__ __forceinline__ void emit_row(float* __restrict__ dst, const ull a[4],
                                         float4 bA, float4 bB) {
    float2 v0 = upk(a[0]), v1 = upk(a[1]), v2 = upk(a[2]), v3 = upk(a[3]);
    float o0 = v0.x + bA.x, o1 = v0.y + bA.y, o2 = v1.x + bA.z, o3 = v1.y + bA.w;
    float o4 = v2.x + bB.x, o5 = v2.y + bB.y, o6 = v3.x + bB.z, o7 = v3.y + bB.w;
    if (RELU) {
        o0 = fmaxf(o0, 0.f); o1 = fmaxf(o1, 0.f); o2 = fmaxf(o2, 0.f); o3 = fmaxf(o3, 0.f);
        o4 = fmaxf(o4, 0.f); o5 = fmaxf(o5, 0.f); o6 = fmaxf(o6, 0.f); o7 = fmaxf(o7, 0.f);
    }
    *reinterpret_cast<float4*>(dst)     = make_float4(o0, o1, o2, o3);
    *reinterpret_cast<float4*>(dst + 4) = make_float4(o4, o5, o6, o7);
}

template<int K, int LDX, bool RELU>
__device__ __forceinline__ void gemm_block8(const float* __restrict__ X,
                                            const float* __restrict__ W,
                                            const float* __restrict__ bias,
                                            float* __restrict__ Y, int tid) {
    const int c0 = (tid & 7) * 8;
    const int rb = (tid >> 3) * 2;
    ull a0[4] = {0, 0, 0, 0};
    ull a1[4] = {0, 0, 0, 0};
    gemm_acc8<K, LDX>(X, W, a0, a1, c0, rb);
    float4 bA = *reinterpret_cast<const float4*>(bias + c0);
    float4 bB = *reinterpret_cast<const float4*>(bias + c0 + 4);
    emit_row<RELU>(Y + rb * STR + c0, a0, bA, bB);
    emit_row<RELU>(Y + (rb + 1) * STR + c0, a1, bA, bB);
}

// residual + LayerNorm: Xs[r] = LN(Yd[r] + Xs[r]); warp w rows w*8..w*8+7, stride STR
__device__ __forceinline__ void ln_block(const float* __restrict__ Yd, float* __restrict__ Xs,
                                         const float* __restrict__ g, const float* __restrict__ be,
                                         int w, int l) {
    float g0 = g[l], g1v = g[l + 32], e0 = be[l], e1v = be[l + 32];
#pragma unroll
    for (int i = 0; i < 8; ++i) {
        int r = w * 8 + i;
        float v0 = Yd[r * STR + l]      + Xs[r * STR + l];
        float v1 = Yd[r * STR + 32 + l] + Xs[r * STR + 32 + l];
        float s = v0 + v1;
#pragma unroll
        for (int o = 16; o >= 1; o >>= 1) s += __shfl_xor_sync(0xffffffffu, s, o);
        float m = s * (1.f / 64.f);
        float d0 = v0 - m, d1 = v1 - m;
        float q = d0 * d0 + d1 * d1;
#pragma unroll
        for (int o = 16; o >= 1; o >>= 1) q += __shfl_xor_sync(0xffffffffu, q, o);
        float inv = rsqrtf(q * (1.f / 64.f) + LN_EPS);
        Xs[r * STR + l]      = d0 * inv * g0 + e0;
        Xs[r * STR + 32 + l] = d1 * inv * g1v + e1v;
    }
}

extern "C" __global__ void __launch_bounds__(NT, 1)
radiance_kernel(const float* __restrict__ query, const float* __restrict__ latent,
                const float* __restrict__ W1, const float* __restrict__ b1,
                const float* __restrict__ Wq, const float* __restrict__ bq,
                const float* __restrict__ Wk, const float* __restrict__ bk,
                const float* __restrict__ Wv, const float* __restrict__ bv,
                const float* __restrict__ Wo, const float* __restrict__ bo,
                const float* __restrict__ fW1, const float* __restrict__ fb1,
                const float* __restrict__ fW2, const float* __restrict__ fb2,
                const float* __restrict__ g1, const float* __restrict__ be1,
                const float* __restrict__ g2, const float* __restrict__ be2,
                const float* __restrict__ cWq, const float* __restrict__ cbq,
                const float* __restrict__ cWk, const float* __restrict__ cbk,
                const float* __restrict__ cWv, const float* __restrict__ cbv,
                const float* __restrict__ cWo, const float* __restrict__ cbo,
                const float* __restrict__ Wc, const float* __restrict__ bc,
                const float* __restrict__ Ws, const float* __restrict__ bs,
                float* __restrict__ out) {
    extern __shared__ float smem[];
    float* SX  = smem + SX_OFF;
    float* ST0 = smem + ST0_OFF;
    float* ST1 = smem + ST1_OFF;
    float* ST2 = smem + ST2_OFF;
    float* SW0 = smem + SW_OFF;
    float* SW1 = SW0 + 4096;
    float* SW2 = SW0 + 8192;
    float* SW3 = SW0 + 12288;
    float* SP  = smem + SP_OFF;
    float* SQI = smem + SQI_OFF;
    float* SCA = smem + SCA_OFF;

    const int tid = threadIdx.x;
    const int w = tid >> 5;     // warp == local batch (0..15)
    const int l = tid & 31;
    const int b0 = blockIdx.x * NB;
    const int c0 = (tid & 7) * 8;
    const int rb = (tid >> 3) * 2;

    float* attn_out = out + OFF_ATTN;

    // ================= Stage 0: x = relu(latent @ W1 + b1) =================
    {
        ull a0[4] = {0, 0, 0, 0};
        ull a1[4] = {0, 0, 0, 0};
        for (int ch = 0; ch < 4; ++ch) {
            __syncthreads();
            cp_f4(SW0, W1 + ch * 8192, 2048, tid);    // W1 rows ch*128..+128 -> [128][64]
            // latent chunk [128 rows][128 k] -> ST0, stride 132 (conflict-free)
            for (int i = tid; i < 4096; i += NT) {
                int r = i >> 5, j = i & 31;
                *reinterpret_cast<float4*>(ST0 + r * 132 + j * 4) =
                    *reinterpret_cast<const float4*>(latent + (size_t)(b0 * 8 + r) * 512 + ch * 128 + j * 4);
            }
            __syncthreads();
            gemm_acc8<128, 132>(ST0, SW0, a0, a1, c0, rb);
        }
        float4 bA = *reinterpret_cast<const float4*>(b1 + c0);
        float4 bB = *reinterpret_cast<const float4*>(b1 + c0 + 4);
        emit_row<true>(SX + rb * STR + c0, a0, bA, bB);
        emit_row<true>(SX + (rb + 1) * STR + c0, a1, bA, bB);
    }

    // ================= 4 transformer layers =================
    for (int li = 0; li < 4; ++li) {
        const float* Wq_i = Wq + li * 16384;
        const float* Wk_i = Wk + li * 16384;
        const float* Wv_i = Wv + li * 16384;
        const float* Wo_i = Wo + li * 16384;

        ull y0[4] = {0, 0, 0, 0};   // O-projection accumulators (persist over heads)
        ull y1[4] = {0, 0, 0, 0};

        for (int h = 0; h < 4; ++h) {
            __syncthreads();
            cp_slice(SW0, Wq_i + h * 64, tid);
            cp_slice(SW1, Wk_i + h * 64, tid);
            cp_slice(SW2, Wv_i + h * 64, tid);
            cp_f4(SW3, Wo_i + h * 4096, 1024, tid);   // Wo rows h*64..+64
            __syncthreads();
            gemm_block8<64, STR, false>(SX, SW0, bq + li * 256 + h * 64, ST0, tid); // Q
            gemm_block8<64, STR, false>(SX, SW1, bk + li * 256 + h * 64, ST1, tid); // K
            gemm_block8<64, STR, false>(SX, SW2, bv + li * 256 + h * 64, ST2, tid); // V
            __syncthreads();

            // ---- attention per warp (= batch) ----
            {
                const float* qB = ST0 + (w * 8) * STR;
                const float* kB = ST1 + (w * 8) * STR;
                const float* vB = ST2 + (w * 8) * STR;
                const int qi = l >> 3, kj = l & 7;
                float s0 = 0.f, s1 = 0.f;
#pragma unroll
                for (int d4 = 0; d4 < 64; d4 += 4) {
                    float4 kv = *reinterpret_cast<const float4*>(kB + kj * STR + d4);
                    float4 q0 = *reinterpret_cast<const float4*>(qB + qi * STR + d4);
                    float4 q1 = *reinterpret_cast<const float4*>(qB + (qi + 4) * STR + d4);
                    s0 += q0.x * kv.x + q0.y * kv.y + q0.z * kv.z + q0.w * kv.w;
                    s1 += q1.x * kv.x + q1.y * kv.y + q1.z * kv.z + q1.w * kv.w;
                }
                s0 *= SCALE_ATT; s1 *= SCALE_ATT;
                float m0 = s0, m1 = s1;
#pragma unroll
                for (int o = 1; o < 8; o <<= 1) {
                    m0 = fmaxf(m0, __shfl_xor_sync(0xffffffffu, m0, o));
                    m1 = fmaxf(m1, __shfl_xor_sync(0xffffffffu, m1, o));
                }
                float e0 = __expf(s0 - m0), e1 = __expf(s1 - m1);
                float t0 = e0, t1 = e1;
#pragma unroll
                for (int o = 1; o < 8; o <<= 1) {
                    t0 += __shfl_xor_sync(0xffffffffu, t0, o);
                    t1 += __shfl_xor_sync(0xffffffffu, t1, o);
                }
                float p0 = e0 / t0, p1 = e1 / t1;
                SP[w * 64 + l]      = p0;
                SP[w * 64 + 32 + l] = p1;
                size_t ab = (size_t)(b0 + w) * 1024 + li * 256 + h * 64;
                attn_out[ab + l]      = p0;
                attn_out[ab + 32 + l] = p1;
                __syncwarp();
                // ctx = P @ V   (kk-outer: V loads reused across 8 q-rows)
                float acc0[8], acc1[8];
#pragma unroll
                for (int qq = 0; qq < 8; ++qq) { acc0[qq] = 0.f; acc1[qq] = 0.f; }
#pragma unroll
                for (int kk = 0; kk < 8; ++kk) {
                    float v0 = vB[kk * STR + l];
                    float v1 = vB[kk * STR + 32 + l];
#pragma unroll
                    for (int qq = 0; qq < 8; ++qq) {
                        float p = SP[w * 64 + qq * 8 + kk];
                        acc0[qq] += p * v0;
                        acc1[qq] += p * v1;
                    }
                }
#pragma unroll
                for (int qq = 0; qq < 8; ++qq) {       // ctx overwrites own-warp Q rows
                    ST0[(w * 8 + qq) * STR + l]      = acc0[qq];
                    ST0[(w * 8 + qq) * STR + 32 + l] = acc1[qq];
                }
            }
            __syncthreads();
            // accumulate O-projection: Y += ctx_h @ Wo[h]
            gemm_acc8<64, STR>(ST0, SW3, y0, y1, c0, rb);
        } // heads

        // Y + bias -> ST1, then LN into SX
        {
            float4 bA = *reinterpret_cast<const float4*>(bo + li * 64 + c0);
            float4 bB = *reinterpret_cast<const float4*>(bo + li * 64 + c0 + 4);
            emit_row<false>(ST1 + rb * STR + c0, y0, bA, bB);
            emit_row<false>(ST1 + (rb + 1) * STR + c0, y1, bA, bB);
        }
        __syncthreads();
        ln_block(ST1, SX, g1 + li * 64, be1 + li * 64, w, l);
        cp_f4(SW0, fW1 + li * 4096, 1024, tid);
        cp_f4(SW1, fW2 + li * 4096, 1024, tid);
        __syncthreads();
        gemm_block8<64, STR, true>(SX, SW0, fb1 + li * 64, ST0, tid);   // h1 = relu(x@fW1+b)
        __syncthreads();
        gemm_block8<64, STR, false>(ST0, SW1, fb2 + li * 64, ST1, tid); // y2
        __syncthreads();
        ln_block(ST1, SX, g2 + li * 64, be2 + li * 64, w, l);
    } // layers

    // load query rows
    for (int i = tid; i < NB * 64; i += NT)
        SQI[i] = query[(size_t)(b0 + (i >> 6)) * 64 + (i & 63)];

    // ================= Cross attention (ca accumulated in regs) =================
    float ca0 = 0.f, ca1 = 0.f;
    for (int h = 0; h < 4; ++h) {
        __syncthreads();
        cp_slice(SW0, cWq + h * 64, tid);
        cp_slice(SW1, cWk + h * 64, tid);
        cp_slice(SW2, cWv + h * 64, tid);
        cp_f4(SW3, cWo + h * 4096, 1024, tid);
        __syncthreads();
        gemm_block8<64, STR, false>(SX, SW1, cbk + h * 64, ST0, tid); // Kc
        gemm_block8<64, STR, false>(SX, SW2, cbv + h * 64, ST1, tid); // Vc
        // Qc per warp: 1 row x 64 cols
        for (int c = l; c < 64; c += 32) {
            float a = 0.f;
#pragma unroll 8
            for (int k2 = 0; k2 < 64; ++k2) a += SQI[w * 64 + k2] * SW0[k2 * 64 + c];
            ST2[w * STR + c] = a + cbq[h * 64 + c];
        }
        __syncthreads();
        // 1x8 attention per warp
        {
            const int j = l >> 2, part = l & 3;
            const float* qrow = ST2 + w * STR;
            const float* kB = ST0 + (w * 8) * STR;
            float sc = 0.f;
#pragma unroll
            for (int d = part * 16; d < part * 16 + 16; ++d) sc += qrow[d] * kB[j * STR + d];
            sc += __shfl_xor_sync(0xffffffffu, sc, 1);
            sc += __shfl_xor_sync(0xffffffffu, sc, 2);
            sc *= SCALE_ATT;
            if (part == 0) SP[w * 64 + j] = sc;
            __syncwarp();
            float mx = -1e30f;
#pragma unroll
            for (int jj = 0; jj < 8; ++jj) mx = fmaxf(mx, SP[w * 64 + jj]);
            float pe[8], ssum = 0.f;
#pragma unroll
            for (int jj = 0; jj < 8; ++jj) { pe[jj] = __expf(SP[w * 64 + jj] - mx); ssum += pe[jj]; }
            float inv = 1.f / ssum;
            const float* vB = ST1 + (w * 8) * STR;
            for (int c = l; c < 64; c += 32) {
                float a = 0.f;
#pragma unroll
                for (int jj = 0; jj < 8; ++jj) a += pe[jj] * vB[jj * STR + c];
                SCA[w * 64 + c] = a * inv;
            }
            __syncwarp();
            // ca += ctx_h @ cWo[h]
#pragma unroll 8
            for (int k2 = 0; k2 < 64; ++k2) {
                float cv = SCA[w * 64 + k2];
                ca0 += cv * SW3[k2 * 64 + l];
                ca1 += cv * SW3[k2 * 64 + 32 + l];
            }
        }
    }
    // heads: color + sigma
    {
        float a0 = fmaxf(ca0 + cbo[l], 0.f);
        float a1 = fmaxf(ca1 + cbo[l + 32], 0.f);
#pragma unroll
        for (int cc = 0; cc < 3; ++cc) {
            float p = a0 * Wc[l * 3 + cc] + a1 * Wc[(l + 32) * 3 + cc];
#pragma unroll
            for (int o = 16; o >= 1; o >>= 1) p += __shfl_xor_sync(0xffffffffu, p, o);
            if (l == 0) out[OFF_COLOR + (size_t)(b0 + w) * 3 + cc] = p + bc[cc];
        }
        float m0 = -1e30f, m1 = -1e30f;
#pragma unroll
        for (int s2 = 0; s2 < 8; ++s2) {
            m0 = fmaxf(m0, SX[(w * 8 + s2) * STR + l]);
            m1 = fmaxf(m1, SX[(w * 8 + s2) * STR + 32 + l]);
        }
        float p = m0 * Ws[l] + m1 * Ws[l + 32];
#pragma unroll
        for (int o = 16; o >= 1; o >>= 1) p += __shfl_xor_sync(0xffffffffu, p, o);
        if (l == 0) out[OFF_SIGMA + b0 + w] = p + bs[0];
    }
    // final out activations
    for (int i = tid; i < NB * 512; i += NT) {
        int r = i >> 6, c = i & 63;
        out[OFF_OUT + (size_t)b0 * 512 + i] = SX[r * STR + c];
    }
}

extern "C" void kernel_launch(void* const* d_in, const int* in_sizes, int n_in,
                              void* d_out, int out_size) {
    (void)in_sizes; (void)n_in; (void)out_size;
    const float* query  = (const float*)d_in[0];
    const float* latent = (const float*)d_in[1];
    const float* W1  = (const float*)d_in[2];
    const float* b1  = (const float*)d_in[3];
    const float* Wq  = (const float*)d_in[4];
    const float* bq  = (const float*)d_in[5];
    const float* Wk  = (const float*)d_in[6];
    const float* bk  = (const float*)d_in[7];
    const float* Wv  = (const float*)d_in[8];
    const float* bv  = (const float*)d_in[9];
    const float* Wo  = (const float*)d_in[10];
    const float* bo  = (const float*)d_in[11];
    const float* fW1 = (const float*)d_in[12];
    const float* fb1 = (const float*)d_in[13];
    const float* fW2 = (const float*)d_in[14];
    const float* fb2 = (const float*)d_in[15];
    const float* g1  = (const float*)d_in[16];
    const float* be1 = (const float*)d_in[17];
    const float* g2  = (const float*)d_in[18];
    const float* be2 = (const float*)d_in[19];
    const float* cWq = (const float*)d_in[20];
    const float* cbq = (const float*)d_in[21];
    const float* cWk = (const float*)d_in[22];
    const float* cbk = (const float*)d_in[23];
    const float* cWv = (const float*)d_in[24];
    const float* cbv = (const float*)d_in[25];
    const float* cWo = (const float*)d_in[26];
    const float* cbo = (const float*)d_in[27];
    const float* Wc  = (const float*)d_in[28];
    const float* bc  = (const float*)d_in[29];
    const float* Ws  = (const float*)d_in[30];
    const float* bs  = (const float*)d_in[31];
    float* out = (float*)d_out;

    const int smem_bytes = SMEM_FLOATS * sizeof(float);
    cudaFuncSetAttribute(radiance_kernel, cudaFuncAttributeMaxDynamicSharedMemorySize, smem_bytes);

    dim3 grid(BB / NB);
    dim3 block(NT);
    radiance_kernel<<<grid, block, smem_bytes>>>(
        query, latent, W1, b1, Wq, bq, Wk, bk, Wv, bv, Wo, bo,
        fW1, fb1, fW2, fb2, g1, be1, g2, be2,
        cWq, cbq, cWk, cbk, cWv, cbv, cWo, cbo, Wc, bc, Ws, bs, out);
}